// round 5
// baseline (speedup 1.0000x reference)
#include <cuda_runtime.h>
#include <cuda_bf16.h>
#include <mma.h>
#include <cstdint>
#include <cstddef>
#include <math_constants.h>

using namespace nvcuda;

// Problem constants
static constexpr int B  = 4;
static constexpr int S  = 2048;
static constexpr int E  = 1024;
static constexpr int H  = 16;
static constexpr int DK = 64;
static constexpr int BH = B * H;      // 64
static constexpr int M_TOK = B * S;   // 8192

// ---------------- scratch (device globals; no cudaMalloc allowed) ----------------
__device__ __nv_bfloat16 g_xhi[(size_t)M_TOK * E], g_xlo[(size_t)M_TOK * E];
__device__ __nv_bfloat16 g_Wqt_hi[(size_t)3 * E * E], g_Wqt_lo[(size_t)3 * E * E];
__device__ __nv_bfloat16 g_Wot_hi[(size_t)E * E],     g_Wot_lo[(size_t)E * E];
__device__ __nv_bfloat16 g_Qhi [(size_t)BH * S * DK], g_Qlo [(size_t)BH * S * DK];
__device__ __nv_bfloat16 g_Khi [(size_t)BH * S * DK], g_Klo [(size_t)BH * S * DK];
__device__ __nv_bfloat16 g_Vthi[(size_t)BH * DK * S], g_Vtlo[(size_t)BH * DK * S];
__device__ __nv_bfloat16 g_valshi[(size_t)M_TOK * E], g_valslo[(size_t)M_TOK * E];

// ---------------- helpers ----------------
__device__ __forceinline__ uint32_t smem_to_u32(const void* p) {
    uint32_t a;
    asm("{ .reg .u64 t; cvta.to.shared.u64 t, %1; cvt.u32.u64 %0, t; }" : "=r"(a) : "l"(p));
    return a;
}
__device__ __forceinline__ void cp_async16(uint32_t dst, const void* src) {
    asm volatile("cp.async.cg.shared.global [%0], [%1], 16;" :: "r"(dst), "l"(src));
}
#define CP_COMMIT() asm volatile("cp.async.commit_group;" ::: "memory")
#define CP_WAIT(N)  asm volatile("cp.async.wait_group %0;" :: "n"(N) : "memory")

__device__ __forceinline__ void split2(float v, __nv_bfloat16& h, __nv_bfloat16& l) {
    h = __float2bfloat16(v);
    l = __float2bfloat16(v - __bfloat162float(h));
}
__device__ __forceinline__ void pack_split2(float a, float b, uint32_t& hi, uint32_t& lo) {
    __nv_bfloat16 ha, la, hb, lb;
    split2(a, ha, la); split2(b, hb, lb);
    __nv_bfloat162 Hp(ha, hb), Lp(la, lb);
    hi = *reinterpret_cast<uint32_t*>(&Hp);
    lo = *reinterpret_cast<uint32_t*>(&Lp);
}

// ---------------- epilogues for projection GEMMs (BN=128, LDC=136) ----------------
struct EpiQKV {
    const float* bias;
    __device__ void run(int /*z*/, int m0, int n0, int tid, const float* Cs) const {
        #pragma unroll
        for (int it = 0; it < 16; it++) {
            int idx = it * 256 + tid;
            int r = idx >> 5;
            int c4 = (idx & 31) * 4;
            float4 v = *reinterpret_cast<const float4*>(Cs + r * 136 + c4);
            int c = n0 + c4;
            v.x += bias[c]; v.y += bias[c + 1]; v.z += bias[c + 2]; v.w += bias[c + 3];
            int h = c / 192, cc = c - h * 192;
            int t = cc >> 6, d0 = cc & 63;
            int gr = m0 + r;
            int b = gr >> 11, s = gr & 2047;
            int bh = b * H + h;
            if (t == 2) {
                float vv[4] = {v.x, v.y, v.z, v.w};
                #pragma unroll
                for (int i = 0; i < 4; i++) {
                    __nv_bfloat16 hi, lo;
                    split2(vv[i], hi, lo);
                    size_t off = ((size_t)bh * DK + d0 + i) * S + s;
                    g_Vthi[off] = hi;
                    g_Vtlo[off] = lo;
                }
            } else {
                __nv_bfloat16* Dh = (t == 0) ? g_Qhi : g_Khi;
                __nv_bfloat16* Dl = (t == 0) ? g_Qlo : g_Klo;
                uint32_t h0, l0, h1, l1;
                pack_split2(v.x, v.y, h0, l0);
                pack_split2(v.z, v.w, h1, l1);
                size_t off = ((size_t)bh * S + s) * DK + d0;
                *reinterpret_cast<uint2*>(Dh + off) = make_uint2(h0, h1);
                *reinterpret_cast<uint2*>(Dl + off) = make_uint2(l0, l1);
            }
        }
    }
};

struct EpiOut {
    const float* bias;
    float* out;
    __device__ void run(int /*z*/, int m0, int n0, int tid, const float* Cs) const {
        #pragma unroll
        for (int it = 0; it < 16; it++) {
            int idx = it * 256 + tid;
            int r = idx >> 5;
            int c4 = (idx & 31) * 4;
            float4 v = *reinterpret_cast<const float4*>(Cs + r * 136 + c4);
            int c = n0 + c4;
            v.x += bias[c]; v.y += bias[c + 1]; v.z += bias[c + 2]; v.w += bias[c + 3];
            *reinterpret_cast<float4*>(out + (size_t)(m0 + r) * E + c) = v;
        }
    }
};

// ---------------- cp.async pipelined split-bf16 WMMA GEMM ----------------
template<int BM, int BN, class Epi>
__global__ void __launch_bounds__(256)
gemm_async(const __nv_bfloat16* __restrict__ Ahi, const __nv_bfloat16* __restrict__ Alo,
           const __nv_bfloat16* __restrict__ Bhi, const __nv_bfloat16* __restrict__ Blo,
           int K, size_t sAz, size_t sBz, Epi epi)
{
    constexpr int LD = 80;
    constexpr int STG_BYTES = (2 * BM + 2 * BN) * LD * 2;
    constexpr int WM = 32, WN = BN / 2;
    constexpr int MI = WM / 16, NI = WN / 16;
    constexpr int LDC = BN + 8;

    extern __shared__ char smem[];
    const uint32_t sbase = smem_to_u32(smem);
    const int tid = threadIdx.x, wid = tid >> 5;
    const int z = blockIdx.z;
    const int m0 = blockIdx.y * BM, n0 = blockIdx.x * BN;
    const int wm0 = (wid & 3) * WM, wn0 = (wid >> 2) * WN;

    Ahi += (size_t)z * sAz; Alo += (size_t)z * sAz;
    Bhi += (size_t)z * sBz; Blo += (size_t)z * sBz;

    const int nchunks = K >> 6;

    auto stage = [&](int s, int ch) {
        const int k0 = ch << 6;
        const uint32_t sA = sbase + s * STG_BYTES;
        const uint32_t sB = sA + 2 * BM * LD * 2;
        for (int u = tid; u < BM * 8; u += 256) {
            int r = u >> 3, g = u & 7;
            size_t gi = (size_t)(m0 + r) * K + k0 + g * 8;
            uint32_t so = sA + (uint32_t)(r * LD + g * 8) * 2;
            cp_async16(so, Ahi + gi);
            cp_async16(so + BM * LD * 2, Alo + gi);
        }
        for (int u = tid; u < BN * 8; u += 256) {
            int r = u >> 3, g = u & 7;
            size_t gi = (size_t)(n0 + r) * K + k0 + g * 8;
            uint32_t so = sB + (uint32_t)(r * LD + g * 8) * 2;
            cp_async16(so, Bhi + gi);
            cp_async16(so + BN * LD * 2, Blo + gi);
        }
        CP_COMMIT();
    };

    wmma::fragment<wmma::accumulator, 16, 16, 16, float> acc[MI][NI];
    #pragma unroll
    for (int mi = 0; mi < MI; mi++)
        #pragma unroll
        for (int ni = 0; ni < NI; ni++) wmma::fill_fragment(acc[mi][ni], 0.0f);

    stage(0, 0);
    for (int ch = 0; ch < nchunks; ch++) {
        if (ch + 1 < nchunks) { stage((ch + 1) & 1, ch + 1); CP_WAIT(1); }
        else                  { CP_WAIT(0); }
        __syncthreads();

        const __nv_bfloat16* As_hi =
            reinterpret_cast<const __nv_bfloat16*>(smem + (ch & 1) * STG_BYTES);
        const __nv_bfloat16* As_lo = As_hi + BM * LD;
        const __nv_bfloat16* Bs_hi = As_lo + BM * LD;
        const __nv_bfloat16* Bs_lo = Bs_hi + BN * LD;

        #pragma unroll
        for (int ks = 0; ks < 4; ks++) {
            wmma::fragment<wmma::matrix_a, 16, 16, 16, __nv_bfloat16, wmma::row_major> ah[MI], al[MI];
            wmma::fragment<wmma::matrix_b, 16, 16, 16, __nv_bfloat16, wmma::col_major> bh[NI], bl[NI];
            #pragma unroll
            for (int mi = 0; mi < MI; mi++) {
                wmma::load_matrix_sync(ah[mi], As_hi + (wm0 + mi * 16) * LD + ks * 16, LD);
                wmma::load_matrix_sync(al[mi], As_lo + (wm0 + mi * 16) * LD + ks * 16, LD);
            }
            #pragma unroll
            for (int ni = 0; ni < NI; ni++) {
                wmma::load_matrix_sync(bh[ni], Bs_hi + (wn0 + ni * 16) * LD + ks * 16, LD);
                wmma::load_matrix_sync(bl[ni], Bs_lo + (wn0 + ni * 16) * LD + ks * 16, LD);
            }
            #pragma unroll
            for (int mi = 0; mi < MI; mi++)
                #pragma unroll
                for (int ni = 0; ni < NI; ni++) {
                    wmma::mma_sync(acc[mi][ni], ah[mi], bh[ni], acc[mi][ni]);
                    wmma::mma_sync(acc[mi][ni], ah[mi], bl[ni], acc[mi][ni]);
                    wmma::mma_sync(acc[mi][ni], al[mi], bh[ni], acc[mi][ni]);
                }
        }
        __syncthreads();
    }

    float* Cs = reinterpret_cast<float*>(smem);
    #pragma unroll
    for (int mi = 0; mi < MI; mi++)
        #pragma unroll
        for (int ni = 0; ni < NI; ni++)
            wmma::store_matrix_sync(Cs + (wm0 + mi * 16) * LDC + wn0 + ni * 16,
                                    acc[mi][ni], LDC, wmma::mem_row_major);
    __syncthreads();
    epi.run(z, m0, n0, tid, Cs);
}

// ---------------- fused attention: logits + softmax + probs + PV ----------------
// CTA = (z, 128-row strip). Phase A: logits -> attn (raw) + online row (max,sum).
// Phase B: re-read strip (L2-hot), exp-normalize, write probs, PV-accumulate.
__global__ void __launch_bounds__(256)
fused_attn(float* __restrict__ attn,
           const __nv_bfloat16* __restrict__ Qhi, const __nv_bfloat16* __restrict__ Qlo,
           const __nv_bfloat16* __restrict__ Khi, const __nv_bfloat16* __restrict__ Klo,
           const __nv_bfloat16* __restrict__ Vthi, const __nv_bfloat16* __restrict__ Vtlo)
{
    constexpr int LDK = 80;              // Q/K stage leading dim (bf16 elems)
    constexpr int LDA = 136;             // logits scratch / probs leading dim
    constexpr int K_STG = 128 * LDK * 2; // 20480 B per matrix
    constexpr int OFF_K  = 0;            // 2 stages * 2 matrices = 81920
    constexpr int OFF_Q  = 81920;        // 40960
    constexpr int OFF_CS = 122880;       // 69632 (Cs fp32  /  phase-B probs bf16 hi+lo)
    constexpr int OFF_ST = 192512;       // 1024 (row stats)
    constexpr int V_STG  = 34816;        // 64*136*2B * 2(hi/lo)

    extern __shared__ char smem[];
    const uint32_t sbase = smem_to_u32(smem);
    const int tid = threadIdx.x, wid = tid >> 5, lane = tid & 31;
    const int z = blockIdx.z;
    const int m0 = blockIdx.y * 128;
    const int wm0 = (wid & 3) * 32;
    const int wnL = (wid >> 2) * 64;     // logits N offset (2-way split of 128)
    const int wnP = (wid >> 2) * 32;     // PV N offset     (2-way split of 64)

    const __nv_bfloat16* Qh = Qhi + ((size_t)z * S + m0) * DK;
    const __nv_bfloat16* Ql = Qlo + ((size_t)z * S + m0) * DK;
    const __nv_bfloat16* Kh = Khi + (size_t)z * S * DK;
    const __nv_bfloat16* Kl = Klo + (size_t)z * S * DK;
    const __nv_bfloat16* Vh = Vthi + (size_t)z * DK * S;
    const __nv_bfloat16* Vl = Vtlo + (size_t)z * DK * S;
    float* Az = attn + (size_t)z * S * S + (size_t)m0 * S;

    // --- initial stages: Q (once) + K chunk 0
    for (int u = tid; u < 128 * 8; u += 256) {
        int r = u >> 3, g = u & 7;
        uint32_t so = sbase + OFF_Q + (uint32_t)(r * LDK + g * 8) * 2;
        cp_async16(so, Qh + (size_t)r * DK + g * 8);
        cp_async16(so + 20480, Ql + (size_t)r * DK + g * 8);
    }
    CP_COMMIT();
    auto stage_k = [&](int s, int nc) {
        int n0 = nc << 7;
        for (int u = tid; u < 128 * 8; u += 256) {
            int r = u >> 3, g = u & 7;
            uint32_t so = sbase + OFF_K + s * 2 * K_STG + (uint32_t)(r * LDK + g * 8) * 2;
            cp_async16(so, Kh + (size_t)(n0 + r) * DK + g * 8);
            cp_async16(so + K_STG, Kl + (size_t)(n0 + r) * DK + g * 8);
        }
        CP_COMMIT();
    };
    stage_k(0, 0);
    CP_WAIT(0);
    __syncthreads();

    // Q fragments cached in registers for the whole kernel (K = DK = 64)
    wmma::fragment<wmma::matrix_a, 16, 16, 16, __nv_bfloat16, wmma::row_major> qh[4][2], ql[4][2];
    {
        const __nv_bfloat16* sQh = reinterpret_cast<const __nv_bfloat16*>(smem + OFF_Q);
        const __nv_bfloat16* sQl = sQh + 128 * LDK;
        #pragma unroll
        for (int ks = 0; ks < 4; ks++)
            #pragma unroll
            for (int mi = 0; mi < 2; mi++) {
                wmma::load_matrix_sync(qh[ks][mi], sQh + (wm0 + mi * 16) * LDK + ks * 16, LDK);
                wmma::load_matrix_sync(ql[ks][mi], sQl + (wm0 + mi * 16) * LDK + ks * 16, LDK);
            }
    }

    float* Cs = reinterpret_cast<float*>(smem + OFF_CS);
    float rowM[16], rowS[16];
    #pragma unroll
    for (int i = 0; i < 16; i++) { rowM[i] = -CUDART_INF_F; rowS[i] = 0.0f; }

    // ================= phase A: logits + online softmax stats =================
    for (int nc = 0; nc < 16; nc++) {
        if (nc + 1 < 16) { stage_k((nc + 1) & 1, nc + 1); CP_WAIT(1); }
        else             { CP_WAIT(0); }
        __syncthreads();   // K stage ready; also guards Cs reuse vs prev epilogue

        const __nv_bfloat16* sKh =
            reinterpret_cast<const __nv_bfloat16*>(smem + OFF_K + (nc & 1) * 2 * K_STG);
        const __nv_bfloat16* sKl = sKh + 128 * LDK;

        wmma::fragment<wmma::accumulator, 16, 16, 16, float> acc[2][4];
        #pragma unroll
        for (int mi = 0; mi < 2; mi++)
            #pragma unroll
            for (int ni = 0; ni < 4; ni++) wmma::fill_fragment(acc[mi][ni], 0.0f);

        #pragma unroll
        for (int ks = 0; ks < 4; ks++) {
            wmma::fragment<wmma::matrix_b, 16, 16, 16, __nv_bfloat16, wmma::col_major> bh[4], bl[4];
            #pragma unroll
            for (int ni = 0; ni < 4; ni++) {
                wmma::load_matrix_sync(bh[ni], sKh + (wnL + ni * 16) * LDK + ks * 16, LDK);
                wmma::load_matrix_sync(bl[ni], sKl + (wnL + ni * 16) * LDK + ks * 16, LDK);
            }
            #pragma unroll
            for (int mi = 0; mi < 2; mi++)
                #pragma unroll
                for (int ni = 0; ni < 4; ni++) {
                    wmma::mma_sync(acc[mi][ni], qh[ks][mi], bh[ni], acc[mi][ni]);
                    wmma::mma_sync(acc[mi][ni], qh[ks][mi], bl[ni], acc[mi][ni]);
                    wmma::mma_sync(acc[mi][ni], ql[ks][mi], bh[ni], acc[mi][ni]);
                }
        }

        #pragma unroll
        for (int mi = 0; mi < 2; mi++)
            #pragma unroll
            for (int ni = 0; ni < 4; ni++)
                wmma::store_matrix_sync(Cs + (wm0 + mi * 16) * LDA + wnL + ni * 16,
                                        acc[mi][ni], LDA, wmma::mem_row_major);
        __syncthreads();

        const int n0 = nc << 7;
        #pragma unroll
        for (int it = 0; it < 16; it++) {
            int r = it * 8 + wid;
            float4 v = *reinterpret_cast<const float4*>(Cs + r * LDA + lane * 4);
            v.x *= 0.125f; v.y *= 0.125f; v.z *= 0.125f; v.w *= 0.125f;
            *reinterpret_cast<float4*>(Az + (size_t)r * S + n0 + lane * 4) = v;
            float tm = fmaxf(fmaxf(v.x, v.y), fmaxf(v.z, v.w));
            #pragma unroll
            for (int o = 16; o > 0; o >>= 1) tm = fmaxf(tm, __shfl_xor_sync(0xFFFFFFFFu, tm, o));
            float ts = __expf(v.x - tm) + __expf(v.y - tm) + __expf(v.z - tm) + __expf(v.w - tm);
            #pragma unroll
            for (int o = 16; o > 0; o >>= 1) ts += __shfl_xor_sync(0xFFFFFFFFu, ts, o);
            float Mn = fmaxf(rowM[it], tm);
            rowS[it] = rowS[it] * __expf(rowM[it] - Mn) + ts * __expf(tm - Mn);
            rowM[it] = Mn;
        }
    }

    // publish row stats
    float* sM = reinterpret_cast<float*>(smem + OFF_ST);
    float* sI = sM + 128;
    #pragma unroll
    for (int it = 0; it < 16; it++) {
        if (lane == 0) {
            int r = it * 8 + wid;
            sM[r] = rowM[it];
            sI[r] = 1.0f / rowS[it];
        }
    }
    __syncthreads();

    // ================= phase B: probs + PV =================
    __nv_bfloat16* Ash = reinterpret_cast<__nv_bfloat16*>(smem + OFF_CS);
    __nv_bfloat16* Asl = Ash + 128 * LDA;

    auto stage_v = [&](int s, int nc) {
        int k0 = nc << 7;
        for (int u = tid; u < 64 * 16; u += 256) {
            int r = u >> 4, g = u & 15;
            uint32_t so = sbase + OFF_K + s * V_STG + (uint32_t)(r * LDA + g * 8) * 2;
            cp_async16(so, Vh + (size_t)r * S + k0 + g * 8);
            cp_async16(so + 17408, Vl + (size_t)r * S + k0 + g * 8);
        }
        CP_COMMIT();
    };
    stage_v(0, 0);

    wmma::fragment<wmma::accumulator, 16, 16, 16, float> pacc[2][2];
    #pragma unroll
    for (int mi = 0; mi < 2; mi++)
        #pragma unroll
        for (int ni = 0; ni < 2; ni++) wmma::fill_fragment(pacc[mi][ni], 0.0f);

    for (int nc = 0; nc < 16; nc++) {
        const int n0 = nc << 7;
        // probs: read raw logits (L2-hot), normalize, write back, split to smem
        #pragma unroll
        for (int it = 0; it < 16; it++) {
            int j = it * 256 + tid;
            int r = j >> 5, c4 = (j & 31) * 4;
            float m = sM[r], inv = sI[r];
            float* src = Az + (size_t)r * S + n0 + c4;
            float4 v = *reinterpret_cast<const float4*>(src);
            v.x = __expf(v.x - m) * inv; v.y = __expf(v.y - m) * inv;
            v.z = __expf(v.z - m) * inv; v.w = __expf(v.w - m) * inv;
            *reinterpret_cast<float4*>(src) = v;
            uint32_t h0, l0, h1, l1;
            pack_split2(v.x, v.y, h0, l0);
            pack_split2(v.z, v.w, h1, l1);
            *reinterpret_cast<uint2*>(Ash + r * LDA + c4) = make_uint2(h0, h1);
            *reinterpret_cast<uint2*>(Asl + r * LDA + c4) = make_uint2(l0, l1);
        }
        CP_WAIT(0);
        __syncthreads();
        if (nc + 1 < 16) stage_v((nc + 1) & 1, nc + 1);

        const __nv_bfloat16* Bsh =
            reinterpret_cast<const __nv_bfloat16*>(smem + OFF_K + (nc & 1) * V_STG);
        const __nv_bfloat16* Bsl = Bsh + 64 * LDA;

        #pragma unroll
        for (int ks = 0; ks < 8; ks++) {
            wmma::fragment<wmma::matrix_a, 16, 16, 16, __nv_bfloat16, wmma::row_major> ah[2], al[2];
            wmma::fragment<wmma::matrix_b, 16, 16, 16, __nv_bfloat16, wmma::col_major> bh[2], bl[2];
            #pragma unroll
            for (int mi = 0; mi < 2; mi++) {
                wmma::load_matrix_sync(ah[mi], Ash + (wm0 + mi * 16) * LDA + ks * 16, LDA);
                wmma::load_matrix_sync(al[mi], Asl + (wm0 + mi * 16) * LDA + ks * 16, LDA);
            }
            #pragma unroll
            for (int ni = 0; ni < 2; ni++) {
                wmma::load_matrix_sync(bh[ni], Bsh + (wnP + ni * 16) * LDA + ks * 16, LDA);
                wmma::load_matrix_sync(bl[ni], Bsl + (wnP + ni * 16) * LDA + ks * 16, LDA);
            }
            #pragma unroll
            for (int mi = 0; mi < 2; mi++)
                #pragma unroll
                for (int ni = 0; ni < 2; ni++) {
                    wmma::mma_sync(pacc[mi][ni], ah[mi], bh[ni], pacc[mi][ni]);
                    wmma::mma_sync(pacc[mi][ni], ah[mi], bl[ni], pacc[mi][ni]);
                    wmma::mma_sync(pacc[mi][ni], al[mi], bh[ni], pacc[mi][ni]);
                }
        }
        __syncthreads();
    }

    // PV epilogue -> g_vals hi/lo
    float* Co = reinterpret_cast<float*>(smem + OFF_CS);
    #pragma unroll
    for (int mi = 0; mi < 2; mi++)
        #pragma unroll
        for (int ni = 0; ni < 2; ni++)
            wmma::store_matrix_sync(Co + (wm0 + mi * 16) * 72 + wnP + ni * 16,
                                    pacc[mi][ni], 72, wmma::mem_row_major);
    __syncthreads();

    const int bb = z >> 4, hh = z & 15;
    #pragma unroll
    for (int it = 0; it < 8; it++) {
        int idx = it * 256 + tid;
        int r = idx >> 4;
        int c4 = (idx & 15) * 4;
        float4 v = *reinterpret_cast<const float4*>(Co + r * 72 + c4);
        uint32_t h0, l0, h1, l1;
        pack_split2(v.x, v.y, h0, l0);
        pack_split2(v.z, v.w, h1, l1);
        size_t off = (size_t)(bb * S + m0 + r) * E + hh * DK + c4;
        *reinterpret_cast<uint2*>(g_valshi + off) = make_uint2(h0, h1);
        *reinterpret_cast<uint2*>(g_valslo + off) = make_uint2(l0, l1);
    }
}

// ---------------- pre-kernels ----------------
__global__ void __launch_bounds__(256)
split_kernel(const float* __restrict__ src, __nv_bfloat16* __restrict__ dh,
             __nv_bfloat16* __restrict__ dl, size_t n)
{
    size_t i = ((size_t)blockIdx.x * 256 + threadIdx.x) * 4;
    if (i >= n) return;
    float4 v = *reinterpret_cast<const float4*>(src + i);
    uint32_t h0, l0, h1, l1;
    pack_split2(v.x, v.y, h0, l0);
    pack_split2(v.z, v.w, h1, l1);
    *reinterpret_cast<uint2*>(dh + i) = make_uint2(h0, h1);
    *reinterpret_cast<uint2*>(dl + i) = make_uint2(l0, l1);
}

__global__ void __launch_bounds__(256)
transpose_split(const float* __restrict__ W, __nv_bfloat16* __restrict__ Th,
                __nv_bfloat16* __restrict__ Tl, int R, int C)
{
    __shared__ float t[32][33];
    int c0 = blockIdx.x * 32, r0 = blockIdx.y * 32;
    int tx = threadIdx.x & 31, ty = threadIdx.x >> 5;
    for (int j = ty; j < 32; j += 8)
        t[j][tx] = W[(size_t)(r0 + j) * C + c0 + tx];
    __syncthreads();
    for (int j = ty; j < 32; j += 8) {
        float v = t[tx][j];
        __nv_bfloat16 hh, ll;
        split2(v, hh, ll);
        size_t o = (size_t)(c0 + j) * R + r0 + tx;
        Th[o] = hh;
        Tl[o] = ll;
    }
}

// ---------------- launch ----------------
extern "C" void kernel_launch(void* const* d_in, const int* /*in_sizes*/, int /*n_in*/,
                              void* d_out, int /*out_size*/)
{
    const float* x    = (const float*)d_in[0];
    const float* Wqkv = (const float*)d_in[1];
    const float* bqkv = (const float*)d_in[2];
    const float* Wout = (const float*)d_in[3];
    const float* bout = (const float*)d_in[4];

    float* out  = (float*)d_out;
    float* attn = out + (size_t)M_TOK * E;

    __nv_bfloat16 *xhi, *xlo, *Wqh, *Wql, *Woh, *Wol;
    __nv_bfloat16 *Qhi, *Qlo, *Khi, *Klo, *Vthi, *Vtlo, *Vh, *Vl;
    cudaGetSymbolAddress((void**)&xhi,  g_xhi);
    cudaGetSymbolAddress((void**)&xlo,  g_xlo);
    cudaGetSymbolAddress((void**)&Wqh,  g_Wqt_hi);
    cudaGetSymbolAddress((void**)&Wql,  g_Wqt_lo);
    cudaGetSymbolAddress((void**)&Woh,  g_Wot_hi);
    cudaGetSymbolAddress((void**)&Wol,  g_Wot_lo);
    cudaGetSymbolAddress((void**)&Qhi,  g_Qhi);
    cudaGetSymbolAddress((void**)&Qlo,  g_Qlo);
    cudaGetSymbolAddress((void**)&Khi,  g_Khi);
    cudaGetSymbolAddress((void**)&Klo,  g_Klo);
    cudaGetSymbolAddress((void**)&Vthi, g_Vthi);
    cudaGetSymbolAddress((void**)&Vtlo, g_Vtlo);
    cudaGetSymbolAddress((void**)&Vh,   g_valshi);
    cudaGetSymbolAddress((void**)&Vl,   g_valslo);

    constexpr int SM_BIG  = 2 * (2 * 128 + 2 * 128) * 80 * 2;   // 163840
    constexpr int SM_FUSE = 193536;
    cudaFuncSetAttribute(gemm_async<128, 128, EpiQKV>,
                         cudaFuncAttributeMaxDynamicSharedMemorySize, SM_BIG);
    cudaFuncSetAttribute(gemm_async<128, 128, EpiOut>,
                         cudaFuncAttributeMaxDynamicSharedMemorySize, SM_BIG);
    cudaFuncSetAttribute(fused_attn,
                         cudaFuncAttributeMaxDynamicSharedMemorySize, SM_FUSE);

    // 0) operand prep
    transpose_split<<<dim3(3 * E / 32, E / 32), 256>>>(Wqkv, Wqh, Wql, E, 3 * E);
    transpose_split<<<dim3(E / 32, E / 32), 256>>>(Wout, Woh, Wol, E, E);
    split_kernel<<<(unsigned)((size_t)M_TOK * E / 4 / 256), 256>>>(x, xhi, xlo, (size_t)M_TOK * E);

    // 1) QKV projection -> split-scatter into Q/K/Vt
    gemm_async<128, 128, EpiQKV><<<dim3(3 * E / 128, M_TOK / 128, 1), 256, SM_BIG>>>(
        xhi, xlo, Wqh, Wql, E, 0, 0, EpiQKV{bqkv});

    // 2) fused: logits -> raw attn + online stats -> probs (attn) + PV values
    fused_attn<<<dim3(1, S / 128, BH), 256, SM_FUSE>>>(
        attn, Qhi, Qlo, Khi, Klo, Vthi, Vtlo);

    // 3) output projection
    gemm_async<128, 128, EpiOut><<<dim3(E / 128, M_TOK / 128, 1), 256, SM_BIG>>>(
        Vh, Vl, Woh, Wol, E, 0, 0, EpiOut{bout, out});
}

// round 6
// speedup vs baseline: 1.2637x; 1.2637x over previous
#include <cuda_runtime.h>
#include <cuda_bf16.h>
#include <mma.h>
#include <cstdint>
#include <cstddef>
#include <math_constants.h>

using namespace nvcuda;

// Problem constants
static constexpr int B  = 4;
static constexpr int S  = 2048;
static constexpr int E  = 1024;
static constexpr int H  = 16;
static constexpr int DK = 64;
static constexpr int BH = B * H;      // 64
static constexpr int M_TOK = B * S;   // 8192

// ---------------- scratch (device globals; no cudaMalloc allowed) ----------------
__device__ __nv_bfloat16 g_xhi[(size_t)M_TOK * E], g_xlo[(size_t)M_TOK * E];
__device__ __nv_bfloat16 g_Wqt_hi[(size_t)3 * E * E], g_Wqt_lo[(size_t)3 * E * E];
__device__ __nv_bfloat16 g_Wot_hi[(size_t)E * E],     g_Wot_lo[(size_t)E * E];
__device__ __nv_bfloat16 g_Qhi [(size_t)BH * S * DK], g_Qlo [(size_t)BH * S * DK];
__device__ __nv_bfloat16 g_Khi [(size_t)BH * S * DK], g_Klo [(size_t)BH * S * DK];
__device__ __nv_bfloat16 g_Vthi[(size_t)BH * DK * S], g_Vtlo[(size_t)BH * DK * S];
__device__ __nv_bfloat16 g_valshi[(size_t)M_TOK * E], g_valslo[(size_t)M_TOK * E];
// softmax partials: per (bh, row, 128-col block)
__device__ float g_pm[(size_t)BH * S * 16], g_ps[(size_t)BH * S * 16];
__device__ float g_rm[(size_t)BH * S],      g_ri[(size_t)BH * S];

// ---------------- helpers ----------------
__device__ __forceinline__ uint32_t smem_to_u32(const void* p) {
    uint32_t a;
    asm("{ .reg .u64 t; cvta.to.shared.u64 t, %1; cvt.u32.u64 %0, t; }" : "=r"(a) : "l"(p));
    return a;
}
__device__ __forceinline__ void cp_async16(uint32_t dst, const void* src) {
    asm volatile("cp.async.cg.shared.global [%0], [%1], 16;" :: "r"(dst), "l"(src));
}
#define CP_COMMIT() asm volatile("cp.async.commit_group;" ::: "memory")
#define CP_WAIT(N)  asm volatile("cp.async.wait_group %0;" :: "n"(N) : "memory")

__device__ __forceinline__ void split2(float v, __nv_bfloat16& h, __nv_bfloat16& l) {
    h = __float2bfloat16(v);
    l = __float2bfloat16(v - __bfloat162float(h));
}
__device__ __forceinline__ void pack_split2(float a, float b, uint32_t& hi, uint32_t& lo) {
    __nv_bfloat16 ha, la, hb, lb;
    split2(a, ha, la); split2(b, hb, lb);
    __nv_bfloat162 Hp(ha, hb), Lp(la, lb);
    hi = *reinterpret_cast<uint32_t*>(&Hp);
    lo = *reinterpret_cast<uint32_t*>(&Lp);
}

// ---------------- epilogues for projection GEMMs (BN=128, LDC=136) ----------------
struct EpiQKV {
    const float* bias;
    __device__ void run(int /*z*/, int m0, int n0, int tid, const float* Cs) const {
        #pragma unroll
        for (int it = 0; it < 16; it++) {
            int idx = it * 256 + tid;
            int r = idx >> 5;
            int c4 = (idx & 31) * 4;
            float4 v = *reinterpret_cast<const float4*>(Cs + r * 136 + c4);
            int c = n0 + c4;
            v.x += bias[c]; v.y += bias[c + 1]; v.z += bias[c + 2]; v.w += bias[c + 3];
            int h = c / 192, cc = c - h * 192;
            int t = cc >> 6, d0 = cc & 63;
            int gr = m0 + r;
            int b = gr >> 11, s = gr & 2047;
            int bh = b * H + h;
            if (t == 2) {
                float vv[4] = {v.x, v.y, v.z, v.w};
                #pragma unroll
                for (int i = 0; i < 4; i++) {
                    __nv_bfloat16 hi, lo;
                    split2(vv[i], hi, lo);
                    size_t off = ((size_t)bh * DK + d0 + i) * S + s;
                    g_Vthi[off] = hi;
                    g_Vtlo[off] = lo;
                }
            } else {
                __nv_bfloat16* Dh = (t == 0) ? g_Qhi : g_Khi;
                __nv_bfloat16* Dl = (t == 0) ? g_Qlo : g_Klo;
                uint32_t h0, l0, h1, l1;
                pack_split2(v.x, v.y, h0, l0);
                pack_split2(v.z, v.w, h1, l1);
                size_t off = ((size_t)bh * S + s) * DK + d0;
                *reinterpret_cast<uint2*>(Dh + off) = make_uint2(h0, h1);
                *reinterpret_cast<uint2*>(Dl + off) = make_uint2(l0, l1);
            }
        }
    }
};

struct EpiLogits {
    float* attn;
    __device__ void run(int z, int m0, int n0, int tid, const float* Cs) const {
        float* dst = attn + (size_t)z * S * S;
        const int lane = tid & 31;
        const int nb = n0 >> 7;
        #pragma unroll
        for (int it = 0; it < 16; it++) {
            int idx = it * 256 + tid;
            int r = idx >> 5;          // warp covers one full 128-col row segment
            int c4 = lane * 4;
            float4 v = *reinterpret_cast<const float4*>(Cs + r * 136 + c4);
            v.x *= 0.125f; v.y *= 0.125f; v.z *= 0.125f; v.w *= 0.125f;
            *reinterpret_cast<float4*>(dst + (size_t)(m0 + r) * S + n0 + c4) = v;
            float tm = fmaxf(fmaxf(v.x, v.y), fmaxf(v.z, v.w));
            #pragma unroll
            for (int o = 16; o > 0; o >>= 1) tm = fmaxf(tm, __shfl_xor_sync(0xFFFFFFFFu, tm, o));
            float ts = __expf(v.x - tm) + __expf(v.y - tm) + __expf(v.z - tm) + __expf(v.w - tm);
            #pragma unroll
            for (int o = 16; o > 0; o >>= 1) ts += __shfl_xor_sync(0xFFFFFFFFu, ts, o);
            if (lane == 0) {
                size_t pi = ((size_t)z * S + m0 + r) * 16 + nb;
                g_pm[pi] = tm;
                g_ps[pi] = ts;
            }
        }
    }
};

struct EpiOut {
    const float* bias;
    float* out;
    __device__ void run(int /*z*/, int m0, int n0, int tid, const float* Cs) const {
        #pragma unroll
        for (int it = 0; it < 16; it++) {
            int idx = it * 256 + tid;
            int r = idx >> 5;
            int c4 = (idx & 31) * 4;
            float4 v = *reinterpret_cast<const float4*>(Cs + r * 136 + c4);
            int c = n0 + c4;
            v.x += bias[c]; v.y += bias[c + 1]; v.z += bias[c + 2]; v.w += bias[c + 3];
            *reinterpret_cast<float4*>(out + (size_t)(m0 + r) * E + c) = v;
        }
    }
};

// ---------------- cp.async pipelined split-bf16 WMMA GEMM (BK=32, 2 CTAs/SM) ------
// D[M,N] = A[M,K] * B[N,K]^T ; A,B K-major bf16 hi/lo. 3 passes into fp32 accum.
template<int BM, int BN, class Epi>
__global__ void __launch_bounds__(256, 2)
gemm_async(const __nv_bfloat16* __restrict__ Ahi, const __nv_bfloat16* __restrict__ Alo,
           const __nv_bfloat16* __restrict__ Bhi, const __nv_bfloat16* __restrict__ Blo,
           int K, size_t sAz, size_t sBz, Epi epi)
{
    constexpr int LD = 40;                          // BK=32 + 8 pad
    constexpr int STG_BYTES = (2 * BM + 2 * BN) * LD * 2;
    constexpr int WM = 32, WN = BN / 2;
    constexpr int MI = WM / 16, NI = WN / 16;
    constexpr int LDC = BN + 8;

    extern __shared__ char smem[];
    const uint32_t sbase = smem_to_u32(smem);
    const int tid = threadIdx.x, wid = tid >> 5;
    const int z = blockIdx.z;
    const int m0 = blockIdx.y * BM, n0 = blockIdx.x * BN;
    const int wm0 = (wid & 3) * WM, wn0 = (wid >> 2) * WN;

    Ahi += (size_t)z * sAz; Alo += (size_t)z * sAz;
    Bhi += (size_t)z * sBz; Blo += (size_t)z * sBz;

    const int nchunks = K >> 5;

    auto stage = [&](int s, int ch) {
        const int k0 = ch << 5;
        const uint32_t sA = sbase + s * STG_BYTES;
        const uint32_t sB = sA + 2 * BM * LD * 2;
        for (int u = tid; u < BM * 4; u += 256) {
            int r = u >> 2, g = u & 3;
            size_t gi = (size_t)(m0 + r) * K + k0 + g * 8;
            uint32_t so = sA + (uint32_t)(r * LD + g * 8) * 2;
            cp_async16(so, Ahi + gi);
            cp_async16(so + BM * LD * 2, Alo + gi);
        }
        for (int u = tid; u < BN * 4; u += 256) {
            int r = u >> 2, g = u & 3;
            size_t gi = (size_t)(n0 + r) * K + k0 + g * 8;
            uint32_t so = sB + (uint32_t)(r * LD + g * 8) * 2;
            cp_async16(so, Bhi + gi);
            cp_async16(so + BN * LD * 2, Blo + gi);
        }
        CP_COMMIT();
    };

    wmma::fragment<wmma::accumulator, 16, 16, 16, float> acc[MI][NI];
    #pragma unroll
    for (int mi = 0; mi < MI; mi++)
        #pragma unroll
        for (int ni = 0; ni < NI; ni++) wmma::fill_fragment(acc[mi][ni], 0.0f);

    stage(0, 0);
    for (int ch = 0; ch < nchunks; ch++) {
        if (ch + 1 < nchunks) { stage((ch + 1) & 1, ch + 1); CP_WAIT(1); }
        else                  { CP_WAIT(0); }
        __syncthreads();

        const __nv_bfloat16* As_hi =
            reinterpret_cast<const __nv_bfloat16*>(smem + (ch & 1) * STG_BYTES);
        const __nv_bfloat16* As_lo = As_hi + BM * LD;
        const __nv_bfloat16* Bs_hi = As_lo + BM * LD;
        const __nv_bfloat16* Bs_lo = Bs_hi + BN * LD;

        #pragma unroll
        for (int ks = 0; ks < 2; ks++) {
            wmma::fragment<wmma::matrix_a, 16, 16, 16, __nv_bfloat16, wmma::row_major> ah[MI], al[MI];
            wmma::fragment<wmma::matrix_b, 16, 16, 16, __nv_bfloat16, wmma::col_major> bh[NI], bl[NI];
            #pragma unroll
            for (int mi = 0; mi < MI; mi++) {
                wmma::load_matrix_sync(ah[mi], As_hi + (wm0 + mi * 16) * LD + ks * 16, LD);
                wmma::load_matrix_sync(al[mi], As_lo + (wm0 + mi * 16) * LD + ks * 16, LD);
            }
            #pragma unroll
            for (int ni = 0; ni < NI; ni++) {
                wmma::load_matrix_sync(bh[ni], Bs_hi + (wn0 + ni * 16) * LD + ks * 16, LD);
                wmma::load_matrix_sync(bl[ni], Bs_lo + (wn0 + ni * 16) * LD + ks * 16, LD);
            }
            #pragma unroll
            for (int mi = 0; mi < MI; mi++)
                #pragma unroll
                for (int ni = 0; ni < NI; ni++) {
                    wmma::mma_sync(acc[mi][ni], ah[mi], bh[ni], acc[mi][ni]);
                    wmma::mma_sync(acc[mi][ni], ah[mi], bl[ni], acc[mi][ni]);
                    wmma::mma_sync(acc[mi][ni], al[mi], bh[ni], acc[mi][ni]);
                }
        }
        __syncthreads();
    }

    float* Cs = reinterpret_cast<float*>(smem);
    #pragma unroll
    for (int mi = 0; mi < MI; mi++)
        #pragma unroll
        for (int ni = 0; ni < NI; ni++)
            wmma::store_matrix_sync(Cs + (wm0 + mi * 16) * LDC + wn0 + ni * 16,
                                    acc[mi][ni], LDC, wmma::mem_row_major);
    __syncthreads();
    epi.run(z, m0, n0, tid, Cs);
}

// ---------------- combine per-block softmax partials into per-row (m, 1/sum) -----
__global__ void __launch_bounds__(256)
rowreduce(const float* __restrict__ pm, const float* __restrict__ ps,
          float* __restrict__ rm, float* __restrict__ ri)
{
    int w = (blockIdx.x * 256 + threadIdx.x) >> 5;   // one warp per row
    int lane = threadIdx.x & 31;
    float m = -CUDART_INF_F, s = 0.0f;
    if (lane < 16) {
        m = pm[(size_t)w * 16 + lane];
        s = ps[(size_t)w * 16 + lane];
    }
    float gm = m;
    #pragma unroll
    for (int o = 16; o > 0; o >>= 1) gm = fmaxf(gm, __shfl_xor_sync(0xFFFFFFFFu, gm, o));
    float c = (lane < 16) ? s * __expf(m - gm) : 0.0f;
    #pragma unroll
    for (int o = 16; o > 0; o >>= 1) c += __shfl_xor_sync(0xFFFFFFFFu, c, o);
    if (lane == 0) {
        rm[w] = gm;
        ri[w] = 1.0f / c;
    }
}

// ---------------- PV kernel: fused softmax + probs write-back + split-bf16 WMMA ----
// values[z](128 rows, 64 cols) = softmax(logits) @ V ; also writes probs into attn.
// V staging double-buffered with cp.async; A transform overlaps V loads.
__global__ void __launch_bounds__(256, 2)
gemm_pv(float* __restrict__ attn, const float* __restrict__ rm, const float* __restrict__ ri,
        const __nv_bfloat16* __restrict__ Vthi, const __nv_bfloat16* __restrict__ Vtlo)
{
    constexpr int BM = 128, LD = 80, LDC = 72;
    constexpr int MI = 2, NI = 2;
    constexpr int OFF_A = 0;                        // Ash+Asl: 2*128*80*2 = 40960
    constexpr int OFF_V = 40960;                    // 2 stages * (2*64*80*2 = 20480)
    constexpr int V_STG = 20480;

    extern __shared__ char smem[];
    const uint32_t sbase = smem_to_u32(smem);
    __nv_bfloat16* Ash = reinterpret_cast<__nv_bfloat16*>(smem + OFF_A);
    __nv_bfloat16* Asl = Ash + BM * LD;
    float* Cs = reinterpret_cast<float*>(smem + OFF_A);

    const int tid = threadIdx.x, wid = tid >> 5;
    const int z = blockIdx.z;
    const int m0 = blockIdx.y * BM;
    const int wm0 = (wid & 3) * 32, wn0 = (wid >> 2) * 32;

    float* A = attn + (size_t)z * S * S;
    const __nv_bfloat16* Bh = Vthi + (size_t)z * DK * S;
    const __nv_bfloat16* Bl = Vtlo + (size_t)z * DK * S;

    auto stage_v = [&](int s, int ch) {
        int k0 = ch << 6;
        for (int u = tid; u < 64 * 8; u += 256) {
            int r = u >> 3, g = u & 7;
            uint32_t so = sbase + OFF_V + s * V_STG + (uint32_t)(r * LD + g * 8) * 2;
            cp_async16(so, Bh + (size_t)r * S + k0 + g * 8);
            cp_async16(so + 64 * LD * 2 / 2 * 0 + 10240, Bl + (size_t)r * S + k0 + g * 8);
        }
        CP_COMMIT();
    };

    wmma::fragment<wmma::accumulator, 16, 16, 16, float> acc[MI][NI];
    #pragma unroll
    for (int mi = 0; mi < MI; mi++)
        #pragma unroll
        for (int ni = 0; ni < NI; ni++) wmma::fill_fragment(acc[mi][ni], 0.0f);

    stage_v(0, 0);
    for (int ch = 0; ch < S / 64; ch++) {
        const int k0 = ch << 6;
        if (ch + 1 < S / 64) stage_v((ch + 1) & 1, ch + 1);

        // A transform: read raw logits, normalize, write probs back, split to smem
        for (int u = tid; u < BM * 8; u += 256) {
            int r = u >> 3, g = u & 7;
            size_t rowoff = (size_t)z * S + m0 + r;
            float m = rm[rowoff], rv = ri[rowoff];
            float* src = A + (size_t)(m0 + r) * S + k0 + g * 8;
            float4 v0 = *reinterpret_cast<const float4*>(src);
            float4 v1 = *reinterpret_cast<const float4*>(src + 4);
            v0.x = __expf(v0.x - m) * rv; v0.y = __expf(v0.y - m) * rv;
            v0.z = __expf(v0.z - m) * rv; v0.w = __expf(v0.w - m) * rv;
            v1.x = __expf(v1.x - m) * rv; v1.y = __expf(v1.y - m) * rv;
            v1.z = __expf(v1.z - m) * rv; v1.w = __expf(v1.w - m) * rv;
            *reinterpret_cast<float4*>(src)     = v0;
            *reinterpret_cast<float4*>(src + 4) = v1;
            uint32_t h0, l0, h1, l1, h2, l2, h3, l3;
            pack_split2(v0.x, v0.y, h0, l0);
            pack_split2(v0.z, v0.w, h1, l1);
            pack_split2(v1.x, v1.y, h2, l2);
            pack_split2(v1.z, v1.w, h3, l3);
            *reinterpret_cast<uint4*>(Ash + r * LD + g * 8) = make_uint4(h0, h1, h2, h3);
            *reinterpret_cast<uint4*>(Asl + r * LD + g * 8) = make_uint4(l0, l1, l2, l3);
        }
        if (ch + 1 < S / 64) { CP_WAIT(1); }
        else                 { CP_WAIT(0); }
        __syncthreads();

        const __nv_bfloat16* Bsh =
            reinterpret_cast<const __nv_bfloat16*>(smem + OFF_V + (ch & 1) * V_STG);
        const __nv_bfloat16* Bsl = Bsh + 64 * LD;

        #pragma unroll
        for (int ks = 0; ks < 4; ks++) {
            wmma::fragment<wmma::matrix_a, 16, 16, 16, __nv_bfloat16, wmma::row_major> ah[MI], al[MI];
            wmma::fragment<wmma::matrix_b, 16, 16, 16, __nv_bfloat16, wmma::col_major> bh[NI], bl[NI];
            #pragma unroll
            for (int mi = 0; mi < MI; mi++) {
                wmma::load_matrix_sync(ah[mi], Ash + (wm0 + mi * 16) * LD + ks * 16, LD);
                wmma::load_matrix_sync(al[mi], Asl + (wm0 + mi * 16) * LD + ks * 16, LD);
            }
            #pragma unroll
            for (int ni = 0; ni < NI; ni++) {
                wmma::load_matrix_sync(bh[ni], Bsh + (wn0 + ni * 16) * LD + ks * 16, LD);
                wmma::load_matrix_sync(bl[ni], Bsl + (wn0 + ni * 16) * LD + ks * 16, LD);
            }
            #pragma unroll
            for (int mi = 0; mi < MI; mi++)
                #pragma unroll
                for (int ni = 0; ni < NI; ni++) {
                    wmma::mma_sync(acc[mi][ni], ah[mi], bh[ni], acc[mi][ni]);
                    wmma::mma_sync(acc[mi][ni], ah[mi], bl[ni], acc[mi][ni]);
                    wmma::mma_sync(acc[mi][ni], al[mi], bh[ni], acc[mi][ni]);
                }
        }
        __syncthreads();
    }

    #pragma unroll
    for (int mi = 0; mi < MI; mi++)
        #pragma unroll
        for (int ni = 0; ni < NI; ni++)
            wmma::store_matrix_sync(Cs + (wm0 + mi * 16) * LDC + wn0 + ni * 16,
                                    acc[mi][ni], LDC, wmma::mem_row_major);
    __syncthreads();

    // scatter values -> g_vals hi/lo [B,S,E]
    int b = z >> 4, h = z & 15;
    #pragma unroll
    for (int it = 0; it < 8; it++) {
        int idx = it * 256 + tid;
        int r = idx >> 4;
        int c4 = (idx & 15) * 4;
        float4 v = *reinterpret_cast<const float4*>(Cs + r * LDC + c4);
        uint32_t h0, l0, h1, l1;
        pack_split2(v.x, v.y, h0, l0);
        pack_split2(v.z, v.w, h1, l1);
        size_t off = (size_t)(b * S + m0 + r) * E + h * DK + c4;
        *reinterpret_cast<uint2*>(g_valshi + off) = make_uint2(h0, h1);
        *reinterpret_cast<uint2*>(g_valslo + off) = make_uint2(l0, l1);
    }
}

// ---------------- pre-kernels ----------------
__global__ void __launch_bounds__(256)
split_kernel(const float* __restrict__ src, __nv_bfloat16* __restrict__ dh,
             __nv_bfloat16* __restrict__ dl, size_t n)
{
    size_t i = ((size_t)blockIdx.x * 256 + threadIdx.x) * 4;
    if (i >= n) return;
    float4 v = *reinterpret_cast<const float4*>(src + i);
    uint32_t h0, l0, h1, l1;
    pack_split2(v.x, v.y, h0, l0);
    pack_split2(v.z, v.w, h1, l1);
    *reinterpret_cast<uint2*>(dh + i) = make_uint2(h0, h1);
    *reinterpret_cast<uint2*>(dl + i) = make_uint2(l0, l1);
}

__global__ void __launch_bounds__(256)
transpose_split(const float* __restrict__ W, __nv_bfloat16* __restrict__ Th,
                __nv_bfloat16* __restrict__ Tl, int R, int C)
{
    __shared__ float t[32][33];
    int c0 = blockIdx.x * 32, r0 = blockIdx.y * 32;
    int tx = threadIdx.x & 31, ty = threadIdx.x >> 5;
    for (int j = ty; j < 32; j += 8)
        t[j][tx] = W[(size_t)(r0 + j) * C + c0 + tx];
    __syncthreads();
    for (int j = ty; j < 32; j += 8) {
        float v = t[tx][j];
        __nv_bfloat16 hh, ll;
        split2(v, hh, ll);
        size_t o = (size_t)(c0 + j) * R + r0 + tx;
        Th[o] = hh;
        Tl[o] = ll;
    }
}

// ---------------- launch ----------------
extern "C" void kernel_launch(void* const* d_in, const int* /*in_sizes*/, int /*n_in*/,
                              void* d_out, int /*out_size*/)
{
    const float* x    = (const float*)d_in[0];
    const float* Wqkv = (const float*)d_in[1];
    const float* bqkv = (const float*)d_in[2];
    const float* Wout = (const float*)d_in[3];
    const float* bout = (const float*)d_in[4];

    float* out  = (float*)d_out;
    float* attn = out + (size_t)M_TOK * E;

    __nv_bfloat16 *xhi, *xlo, *Wqh, *Wql, *Woh, *Wol;
    __nv_bfloat16 *Qhi, *Qlo, *Khi, *Klo, *Vthi, *Vtlo, *Vh, *Vl;
    float *pm, *ps, *rm, *ri;
    cudaGetSymbolAddress((void**)&xhi,  g_xhi);
    cudaGetSymbolAddress((void**)&xlo,  g_xlo);
    cudaGetSymbolAddress((void**)&Wqh,  g_Wqt_hi);
    cudaGetSymbolAddress((void**)&Wql,  g_Wqt_lo);
    cudaGetSymbolAddress((void**)&Woh,  g_Wot_hi);
    cudaGetSymbolAddress((void**)&Wol,  g_Wot_lo);
    cudaGetSymbolAddress((void**)&Qhi,  g_Qhi);
    cudaGetSymbolAddress((void**)&Qlo,  g_Qlo);
    cudaGetSymbolAddress((void**)&Khi,  g_Khi);
    cudaGetSymbolAddress((void**)&Klo,  g_Klo);
    cudaGetSymbolAddress((void**)&Vthi, g_Vthi);
    cudaGetSymbolAddress((void**)&Vtlo, g_Vtlo);
    cudaGetSymbolAddress((void**)&Vh,   g_valshi);
    cudaGetSymbolAddress((void**)&Vl,   g_valslo);
    cudaGetSymbolAddress((void**)&pm,   g_pm);
    cudaGetSymbolAddress((void**)&ps,   g_ps);
    cudaGetSymbolAddress((void**)&rm,   g_rm);
    cudaGetSymbolAddress((void**)&ri,   g_ri);

    constexpr int SM_BIG = 2 * (2 * 128 + 2 * 128) * 40 * 2;   // 81920 (2 stages, BK=32)
    constexpr int SM_PV  = 81920;                              // A 40960 + V 2x20480
    cudaFuncSetAttribute(gemm_async<128, 128, EpiQKV>,
                         cudaFuncAttributeMaxDynamicSharedMemorySize, SM_BIG);
    cudaFuncSetAttribute(gemm_async<128, 128, EpiLogits>,
                         cudaFuncAttributeMaxDynamicSharedMemorySize, SM_BIG);
    cudaFuncSetAttribute(gemm_async<128, 128, EpiOut>,
                         cudaFuncAttributeMaxDynamicSharedMemorySize, SM_BIG);
    cudaFuncSetAttribute(gemm_pv,
                         cudaFuncAttributeMaxDynamicSharedMemorySize, SM_PV);

    // 0) operand prep
    transpose_split<<<dim3(3 * E / 32, E / 32), 256>>>(Wqkv, Wqh, Wql, E, 3 * E);
    transpose_split<<<dim3(E / 32, E / 32), 256>>>(Wout, Woh, Wol, E, E);
    split_kernel<<<(unsigned)((size_t)M_TOK * E / 4 / 256), 256>>>(x, xhi, xlo, (size_t)M_TOK * E);

    // 1) QKV projection -> split-scatter into Q/K/Vt
    gemm_async<128, 128, EpiQKV><<<dim3(3 * E / 128, M_TOK / 128, 1), 256, SM_BIG>>>(
        xhi, xlo, Wqh, Wql, E, 0, 0, EpiQKV{bqkv});

    // 2) logits = Q*K^T/8 -> attn (raw), plus per-block softmax partials
    gemm_async<128, 128, EpiLogits><<<dim3(S / 128, S / 128, BH), 256, SM_BIG>>>(
        Qhi, Qlo, Khi, Klo, DK, (size_t)S * DK, (size_t)S * DK, EpiLogits{attn});

    // 3) combine partials -> per-row (max, 1/sum)
    rowreduce<<<(unsigned)((size_t)BH * S * 32 / 256), 256>>>(pm, ps, rm, ri);

    // 4) PV: fused softmax (writes probs into attn) + values GEMM
    gemm_pv<<<dim3(1, S / 128, BH), 256, SM_PV>>>(attn, rm, ri, Vthi, Vtlo);

    // 5) output projection
    gemm_async<128, 128, EpiOut><<<dim3(E / 128, M_TOK / 128, 1), 256, SM_BIG>>>(
        Vh, Vl, Woh, Wol, E, 0, 0, EpiOut{bout, out});
}